// round 1
// baseline (speedup 1.0000x reference)
#include <cuda_runtime.h>
#include <cuda_bf16.h>
#include <math.h>

// Problem constants
#define N_TOK 2048
#define H_DIM 1024
#define E_NUM 8
#define F_DIM 1024
#define TOPK 2
#define THRESHOLD 0.7f

// GEMM tiling
#define BM 64
#define BN 64
#define BK 16

// ---------------- scratch (device globals; no allocation allowed) ----------
__device__ int   g_primary_mask;
__device__ int   g_top_i[N_TOK * 2];
__device__ float g_top_w[N_TOK * 2];
__device__ int   g_tok_e[N_TOK * 2];
__device__ float g_tok_w[N_TOK * 2];
__device__ int   g_list_tok[E_NUM][N_TOK];
__device__ float g_list_w[E_NUM][N_TOK];
__device__ int   g_cnt[E_NUM];
__device__ int   g_off[E_NUM];
__device__ float g_mid[(size_t)N_TOK * TOPK * F_DIM];   // 16 MB scratch

// ---------------- f32x2 packed-FMA helpers (Blackwell FFMA2) ---------------
__device__ __forceinline__ unsigned long long pack2(float x, float y) {
    unsigned long long r;
    asm("mov.b64 %0, {%1, %2};" : "=l"(r) : "f"(x), "f"(y));
    return r;
}
__device__ __forceinline__ unsigned long long ffma2(unsigned long long a,
                                                    unsigned long long b,
                                                    unsigned long long c) {
    unsigned long long d;
    asm("fma.rn.f32x2 %0, %1, %2, %3;" : "=l"(d) : "l"(a), "l"(b), "l"(c));
    return d;
}
__device__ __forceinline__ float2 unpack2(unsigned long long v) {
    float2 f;
    asm("mov.b64 {%0, %1}, %2;" : "=f"(f.x), "=f"(f.y) : "l"(v));
    return f;
}

// ---------------- kernel 0: zero output + mask --------------------------
__global__ void zero_kernel(float* __restrict__ out) {
    float4 z = make_float4(0.f, 0.f, 0.f, 0.f);
    float4* o = (float4*)out;
    int base = blockIdx.x * 1024 + threadIdx.x;
#pragma unroll
    for (int j = 0; j < 4; j++) o[base + j * 256] = z;
    if (blockIdx.x == 0 && threadIdx.x == 0) g_primary_mask = 0;
}

// ---------------- kernel 1: router (logits -> softmax -> top2) ----------
// grid 256 blocks x 256 thr; one warp per token
__global__ void router_kernel(const float* __restrict__ x,
                              const float* __restrict__ gw) {
    __shared__ __align__(16) float gws[E_NUM * H_DIM];
    int tid = threadIdx.x;
    for (int i = tid * 4; i < E_NUM * H_DIM; i += 1024)
        *(float4*)&gws[i] = *(const float4*)&gw[i];
    __syncthreads();

    int warp = tid >> 5, lane = tid & 31;
    int n = blockIdx.x * 8 + warp;
    const float* xp = x + (size_t)n * H_DIM;

    float acc[E_NUM];
#pragma unroll
    for (int e = 0; e < E_NUM; e++) acc[e] = 0.f;

    for (int h = lane * 4; h < H_DIM; h += 128) {
        float4 xv = *(const float4*)&xp[h];
#pragma unroll
        for (int e = 0; e < E_NUM; e++) {
            float4 wv = *(const float4*)&gws[e * H_DIM + h];
            acc[e] += xv.x * wv.x + xv.y * wv.y + xv.z * wv.z + xv.w * wv.w;
        }
    }
#pragma unroll
    for (int e = 0; e < E_NUM; e++)
#pragma unroll
        for (int o = 16; o; o >>= 1) acc[e] += __shfl_xor_sync(~0u, acc[e], o);

    if (lane == 0) {
        float m = acc[0];
#pragma unroll
        for (int e = 1; e < E_NUM; e++) m = fmaxf(m, acc[e]);
        float p[E_NUM];
#pragma unroll
        for (int e = 0; e < E_NUM; e++) p[e] = expf(acc[e] - m);
        // top1 (first max, matches jax.lax.top_k stability)
        int i0 = 0; float b0 = p[0];
#pragma unroll
        for (int e = 1; e < E_NUM; e++) if (p[e] > b0) { b0 = p[e]; i0 = e; }
        int i1 = -1; float b1 = -1.f;
#pragma unroll
        for (int e = 0; e < E_NUM; e++)
            if (e != i0 && p[e] > b1) { b1 = p[e]; i1 = e; }
        // normalized top-k weights: p_i / (p0 + p1)
        float s2 = b0 + b1;
        g_top_i[2 * n] = i0; g_top_i[2 * n + 1] = i1;
        g_top_w[2 * n] = b0 / s2; g_top_w[2 * n + 1] = b1 / s2;
        atomicOr(&g_primary_mask, 1 << i0);
    }
}

// ---------------- kernel 2: reroute + merge + deterministic compaction ---
// single CTA, 256 threads (8 warps, one per expert for compaction)
__global__ void route_kernel(const float* __restrict__ sim) {
    __shared__ int map_s[E_NUM];
    __shared__ int cnt_s[E_NUM];
    int tid = threadIdx.x;
    int mask = g_primary_mask;

    if (tid < E_NUM) {
        int mp;
        if ((mask >> tid) & 1) {
            mp = tid;
        } else {
            float best = -1e30f; int bj = -1;
            for (int j = 0; j < E_NUM; j++)
                if ((mask >> j) & 1) {
                    float v = sim[tid * E_NUM + j];
                    if (v > best) { best = v; bj = j; }   // argmax: first max
                }
            mp = (bj >= 0 && best >= THRESHOLD) ? bj : tid;
        }
        map_s[tid] = mp;
    }
    __syncthreads();

    for (int n = tid; n < N_TOK; n += 256) {
        int i0 = g_top_i[2 * n], i1 = g_top_i[2 * n + 1];
        float w0 = g_top_w[2 * n], w1 = g_top_w[2 * n + 1];
        int e0 = map_s[i0], e1 = map_s[i1];
        if (e0 == e1) { w0 += w1; e1 = -1; }
        g_tok_e[2 * n] = e0; g_tok_e[2 * n + 1] = e1;
        g_tok_w[2 * n] = w0; g_tok_w[2 * n + 1] = w1;
    }
    __syncthreads();

    int warp = tid >> 5, lane = tid & 31;
    int e = warp;   // 8 warps == 8 experts
    int cnt = 0;
    for (int base = 0; base < N_TOK; base += 32) {
        int n = base + lane;
        int e0 = g_tok_e[2 * n], e1 = g_tok_e[2 * n + 1];
        bool f0 = (e0 == e), f1 = (e1 == e);
        bool f = f0 || f1;
        float w = f0 ? g_tok_w[2 * n] : g_tok_w[2 * n + 1];
        unsigned b = __ballot_sync(~0u, f);
        if (f) {
            int pos = cnt + __popc(b & ((1u << lane) - 1));
            g_list_tok[e][pos] = n;
            g_list_w[e][pos] = w;
        }
        cnt += __popc(b);
    }
    if (lane == 0) cnt_s[e] = cnt;
    __syncthreads();
    if (tid == 0) {
        int o = 0;
        for (int i = 0; i < E_NUM; i++) { g_off[i] = o; g_cnt[i] = cnt_s[i]; o += cnt_s[i]; }
    }
}

// ---------------- kernel 3: grouped GEMM gate_up + silu*u ----------------
// grid (F/BN=16, 32, 8), block 256
__global__ __launch_bounds__(256, 2)
void gemm_gu_kernel(const float* __restrict__ x,
                    const float* __restrict__ gup) {
    int e = blockIdx.z;
    int cnt = g_cnt[e];
    int mbase = blockIdx.y * BM;
    if (mbase >= cnt) return;
    int fbase = blockIdx.x * BN;
    int off = g_off[e];

    __shared__ __align__(16) float As[2][BK][BM + 8];
    __shared__ __align__(16) float Bgs[2][BK][BN + 8];
    __shared__ __align__(16) float Bus[2][BK][BN + 8];

    int tid = threadIdx.x;
    int tx = tid & 15, ty = tid >> 4;
    int lrow = tid >> 2, lkg = (tid & 3) * 4;

    int arow = mbase + lrow; if (arow >= cnt) arow = cnt - 1;
    const float* aptr = x + (size_t)g_list_tok[e][arow] * H_DIM;
    const float* bgptr = gup + ((size_t)e * 2 * F_DIM + (fbase + lrow)) * H_DIM;
    const float* buptr = gup + ((size_t)e * 2 * F_DIM + F_DIM + (fbase + lrow)) * H_DIM;

    unsigned long long cg[4][2], cu[4][2];
#pragma unroll
    for (int i = 0; i < 4; i++) { cg[i][0] = 0ull; cg[i][1] = 0ull; cu[i][0] = 0ull; cu[i][1] = 0ull; }

    float4 ra = *(const float4*)(aptr + lkg);
    float4 rg = *(const float4*)(bgptr + lkg);
    float4 ru = *(const float4*)(buptr + lkg);
    As[0][lkg + 0][lrow] = ra.x; As[0][lkg + 1][lrow] = ra.y; As[0][lkg + 2][lrow] = ra.z; As[0][lkg + 3][lrow] = ra.w;
    Bgs[0][lkg + 0][lrow] = rg.x; Bgs[0][lkg + 1][lrow] = rg.y; Bgs[0][lkg + 2][lrow] = rg.z; Bgs[0][lkg + 3][lrow] = rg.w;
    Bus[0][lkg + 0][lrow] = ru.x; Bus[0][lkg + 1][lrow] = ru.y; Bus[0][lkg + 2][lrow] = ru.z; Bus[0][lkg + 3][lrow] = ru.w;
    __syncthreads();

    const int NC = H_DIM / BK;   // 64
    for (int kc = 0; kc < NC; kc++) {
        int cur = kc & 1;
        if (kc < NC - 1) {
            int k0 = (kc + 1) * BK;
            ra = *(const float4*)(aptr + k0 + lkg);
            rg = *(const float4*)(bgptr + k0 + lkg);
            ru = *(const float4*)(buptr + k0 + lkg);
        }
#pragma unroll
        for (int k = 0; k < BK; k++) {
            float4 av = *(const float4*)&As[cur][k][ty * 4];
            unsigned long long a0 = pack2(av.x, av.x);
            unsigned long long a1 = pack2(av.y, av.y);
            unsigned long long a2 = pack2(av.z, av.z);
            unsigned long long a3 = pack2(av.w, av.w);
            unsigned long long bg0 = *(const unsigned long long*)&Bgs[cur][k][tx * 4];
            unsigned long long bg1 = *(const unsigned long long*)&Bgs[cur][k][tx * 4 + 2];
            unsigned long long bu0 = *(const unsigned long long*)&Bus[cur][k][tx * 4];
            unsigned long long bu1 = *(const unsigned long long*)&Bus[cur][k][tx * 4 + 2];
            cg[0][0] = ffma2(a0, bg0, cg[0][0]); cg[0][1] = ffma2(a0, bg1, cg[0][1]);
            cg[1][0] = ffma2(a1, bg0, cg[1][0]); cg[1][1] = ffma2(a1, bg1, cg[1][1]);
            cg[2][0] = ffma2(a2, bg0, cg[2][0]); cg[2][1] = ffma2(a2, bg1, cg[2][1]);
            cg[3][0] = ffma2(a3, bg0, cg[3][0]); cg[3][1] = ffma2(a3, bg1, cg[3][1]);
            cu[0][0] = ffma2(a0, bu0, cu[0][0]); cu[0][1] = ffma2(a0, bu1, cu[0][1]);
            cu[1][0] = ffma2(a1, bu0, cu[1][0]); cu[1][1] = ffma2(a1, bu1, cu[1][1]);
            cu[2][0] = ffma2(a2, bu0, cu[2][0]); cu[2][1] = ffma2(a2, bu1, cu[2][1]);
            cu[3][0] = ffma2(a3, bu0, cu[3][0]); cu[3][1] = ffma2(a3, bu1, cu[3][1]);
        }
        if (kc < NC - 1) {
            int nxt = cur ^ 1;
            As[nxt][lkg + 0][lrow] = ra.x; As[nxt][lkg + 1][lrow] = ra.y; As[nxt][lkg + 2][lrow] = ra.z; As[nxt][lkg + 3][lrow] = ra.w;
            Bgs[nxt][lkg + 0][lrow] = rg.x; Bgs[nxt][lkg + 1][lrow] = rg.y; Bgs[nxt][lkg + 2][lrow] = rg.z; Bgs[nxt][lkg + 3][lrow] = rg.w;
            Bus[nxt][lkg + 0][lrow] = ru.x; Bus[nxt][lkg + 1][lrow] = ru.y; Bus[nxt][lkg + 2][lrow] = ru.z; Bus[nxt][lkg + 3][lrow] = ru.w;
        }
        __syncthreads();
    }

#pragma unroll
    for (int i = 0; i < 4; i++) {
        int m = mbase + ty * 4 + i;
        if (m < cnt) {
            float2 g0 = unpack2(cg[i][0]), g1 = unpack2(cg[i][1]);
            float2 u0 = unpack2(cu[i][0]), u1 = unpack2(cu[i][1]);
            float4 ov;
            ov.x = (g0.x / (1.f + expf(-g0.x))) * u0.x;
            ov.y = (g0.y / (1.f + expf(-g0.y))) * u0.y;
            ov.z = (g1.x / (1.f + expf(-g1.x))) * u1.x;
            ov.w = (g1.y / (1.f + expf(-g1.y))) * u1.y;
            *(float4*)&g_mid[((size_t)(off + m)) * F_DIM + fbase + tx * 4] = ov;
        }
    }
}

// ---------------- kernel 4: grouped GEMM down + weighted scatter-add -----
// grid (H/BN=16, 32, 8), block 256
__global__ __launch_bounds__(256, 2)
void gemm_down_kernel(const float* __restrict__ dp,
                      float* __restrict__ out) {
    int e = blockIdx.z;
    int cnt = g_cnt[e];
    int mbase = blockIdx.y * BM;
    if (mbase >= cnt) return;
    int hbase = blockIdx.x * BN;
    int off = g_off[e];

    __shared__ __align__(16) float As[2][BK][BM + 8];
    __shared__ __align__(16) float Bs[2][BK][BN + 8];

    int tid = threadIdx.x;
    int tx = tid & 15, ty = tid >> 4;
    int lrow = tid >> 2, lkg = (tid & 3) * 4;

    int arow = mbase + lrow; if (arow >= cnt) arow = cnt - 1;
    const float* aptr = g_mid + (size_t)(off + arow) * F_DIM;
    const float* bptr = dp + ((size_t)e * H_DIM + (hbase + lrow)) * F_DIM;

    unsigned long long c[4][2];
#pragma unroll
    for (int i = 0; i < 4; i++) { c[i][0] = 0ull; c[i][1] = 0ull; }

    float4 ra = *(const float4*)(aptr + lkg);
    float4 rb = *(const float4*)(bptr + lkg);
    As[0][lkg + 0][lrow] = ra.x; As[0][lkg + 1][lrow] = ra.y; As[0][lkg + 2][lrow] = ra.z; As[0][lkg + 3][lrow] = ra.w;
    Bs[0][lkg + 0][lrow] = rb.x; Bs[0][lkg + 1][lrow] = rb.y; Bs[0][lkg + 2][lrow] = rb.z; Bs[0][lkg + 3][lrow] = rb.w;
    __syncthreads();

    const int NC = F_DIM / BK;   // 64
    for (int kc = 0; kc < NC; kc++) {
        int cur = kc & 1;
        if (kc < NC - 1) {
            int k0 = (kc + 1) * BK;
            ra = *(const float4*)(aptr + k0 + lkg);
            rb = *(const float4*)(bptr + k0 + lkg);
        }
#pragma unroll
        for (int k = 0; k < BK; k++) {
            float4 av = *(const float4*)&As[cur][k][ty * 4];
            unsigned long long a0 = pack2(av.x, av.x);
            unsigned long long a1 = pack2(av.y, av.y);
            unsigned long long a2 = pack2(av.z, av.z);
            unsigned long long a3 = pack2(av.w, av.w);
            unsigned long long b0 = *(const unsigned long long*)&Bs[cur][k][tx * 4];
            unsigned long long b1 = *(const unsigned long long*)&Bs[cur][k][tx * 4 + 2];
            c[0][0] = ffma2(a0, b0, c[0][0]); c[0][1] = ffma2(a0, b1, c[0][1]);
            c[1][0] = ffma2(a1, b0, c[1][0]); c[1][1] = ffma2(a1, b1, c[1][1]);
            c[2][0] = ffma2(a2, b0, c[2][0]); c[2][1] = ffma2(a2, b1, c[2][1]);
            c[3][0] = ffma2(a3, b0, c[3][0]); c[3][1] = ffma2(a3, b1, c[3][1]);
        }
        if (kc < NC - 1) {
            int nxt = cur ^ 1;
            As[nxt][lkg + 0][lrow] = ra.x; As[nxt][lkg + 1][lrow] = ra.y; As[nxt][lkg + 2][lrow] = ra.z; As[nxt][lkg + 3][lrow] = ra.w;
            Bs[nxt][lkg + 0][lrow] = rb.x; Bs[nxt][lkg + 1][lrow] = rb.y; Bs[nxt][lkg + 2][lrow] = rb.z; Bs[nxt][lkg + 3][lrow] = rb.w;
        }
        __syncthreads();
    }

#pragma unroll
    for (int i = 0; i < 4; i++) {
        int m = mbase + ty * 4 + i;
        if (m < cnt) {
            int tok = g_list_tok[e][m];
            float w = g_list_w[e][m];
            float2 c0 = unpack2(c[i][0]), c1 = unpack2(c[i][1]);
            float* op = out + (size_t)tok * H_DIM + hbase + tx * 4;
            atomicAdd(op + 0, w * c0.x);
            atomicAdd(op + 1, w * c0.y);
            atomicAdd(op + 2, w * c1.x);
            atomicAdd(op + 3, w * c1.y);
        }
    }
}

// ---------------- launch ---------------------------------------------------
extern "C" void kernel_launch(void* const* d_in, const int* in_sizes, int n_in,
                              void* d_out, int out_size) {
    const float* x   = (const float*)d_in[0];   // [2,1024,1024]
    const float* gw  = (const float*)d_in[1];   // [8,1024]
    const float* gup = (const float*)d_in[2];   // [8,2048,1024]
    const float* dp  = (const float*)d_in[3];   // [8,1024,1024]
    const float* sim = (const float*)d_in[4];   // [8,8]
    float* out = (float*)d_out;                  // [2,1024,1024]

    zero_kernel<<<512, 256>>>(out);
    router_kernel<<<256, 256>>>(x, gw);
    route_kernel<<<1, 256>>>(sim);
    dim3 gg(F_DIM / BN, N_TOK / BM, E_NUM);     // (16, 32, 8)
    gemm_gu_kernel<<<gg, 256>>>(x, gup);
    dim3 gd(H_DIM / BN, N_TOK / BM, E_NUM);     // (16, 32, 8)
    gemm_down_kernel<<<gd, 256>>>(dp, out);
}

// round 4
// speedup vs baseline: 1.5894x; 1.5894x over previous
#include <cuda_runtime.h>
#include <cuda_fp16.h>
#include <math.h>
#include <stdint.h>

// Problem constants
#define N_TOK 2048
#define H_DIM 1024
#define E_NUM 8
#define F_DIM 1024
#define THRESHOLD 0.7f

// HMMA tiling: CTA 128(M) x (64 gate + 64 up | 128) ; 8 warps, warp tile 64x32
#define LDK 40                              // padded halves per row (16B-aligned rows, ldmatrix conflict-free)
#define TILE_HALVES (128 * LDK)             // one operand tile
#define OFF_AH 0
#define OFF_AL (TILE_HALVES * 2)            // bytes
#define OFF_BH (2 * TILE_HALVES * 2)
#define OFF_BL (3 * TILE_HALVES * 2)
#define SMEM_BYTES (4 * TILE_HALVES * 2)    // 40960 B

// ---------------- scratch (device globals) ----------------
__device__ int   g_primary_mask;
__device__ int   g_top_i[N_TOK * 2];
__device__ float g_top_w[N_TOK * 2];
__device__ int   g_tok_e[N_TOK * 2];
__device__ float g_tok_w[N_TOK * 2];
__device__ int   g_list_tok[E_NUM][N_TOK];
__device__ float g_list_w[E_NUM][N_TOK];
__device__ int   g_cnt[E_NUM];
__device__ int   g_off[E_NUM];
__device__ float g_mid[(size_t)N_TOK * 2 * F_DIM];   // 16 MB

// ---------------- helpers ----------------
__device__ __forceinline__ uint32_t smem_u32(const void* p) {
    uint32_t a;
    asm("{ .reg .u64 t; cvta.to.shared.u64 t, %1; cvt.u32.u64 %0, t; }" : "=r"(a) : "l"(p));
    return a;
}
__device__ __forceinline__ void ldm4(uint32_t* r, uint32_t addr) {
    asm volatile("ldmatrix.sync.aligned.m8n8.x4.shared.b16 {%0,%1,%2,%3}, [%4];"
                 : "=r"(r[0]), "=r"(r[1]), "=r"(r[2]), "=r"(r[3]) : "r"(addr));
}
__device__ __forceinline__ void mma16816(float* c, const uint32_t* a, const uint32_t* b) {
    asm volatile("mma.sync.aligned.m16n8k16.row.col.f32.f16.f16.f32 "
                 "{%0,%1,%2,%3}, {%4,%5,%6,%7}, {%8,%9}, {%0,%1,%2,%3};"
                 : "+f"(c[0]), "+f"(c[1]), "+f"(c[2]), "+f"(c[3])
                 : "r"(a[0]), "r"(a[1]), "r"(a[2]), "r"(a[3]), "r"(b[0]), "r"(b[1]));
}
__device__ __forceinline__ uint32_t pk(__half x, __half y) {
    __half2 t = __halves2half2(x, y);
    return *reinterpret_cast<uint32_t*>(&t);
}
// split 8 floats into fp16 hi + fp16 lo (residual), packed
__device__ __forceinline__ void cvt8(float4 a, float4 b, uint4& H, uint4& L) {
    float f[8] = {a.x, a.y, a.z, a.w, b.x, b.y, b.z, b.w};
    __half h[8], l[8];
#pragma unroll
    for (int i = 0; i < 8; i++) {
        h[i] = __float2half_rn(f[i]);
        l[i] = __float2half_rn(f[i] - __half2float(h[i]));
    }
    H = make_uint4(pk(h[0], h[1]), pk(h[2], h[3]), pk(h[4], h[5]), pk(h[6], h[7]));
    L = make_uint4(pk(l[0], l[1]), pk(l[2], l[3]), pk(l[4], l[5]), pk(l[6], l[7]));
}

// ---------------- kernel 0: zero output + mask ----------------
__global__ void zero_kernel(float* __restrict__ out) {
    float4 z = make_float4(0.f, 0.f, 0.f, 0.f);
    float4* o = (float4*)out;
    int base = blockIdx.x * 1024 + threadIdx.x;
#pragma unroll
    for (int j = 0; j < 4; j++) o[base + j * 256] = z;
    if (blockIdx.x == 0 && threadIdx.x == 0) g_primary_mask = 0;
}

// ---------------- kernel 1: router ----------------
__global__ void router_kernel(const float* __restrict__ x,
                              const float* __restrict__ gw) {
    __shared__ __align__(16) float gws[E_NUM * H_DIM];
    int tid = threadIdx.x;
    for (int i = tid * 4; i < E_NUM * H_DIM; i += 1024)
        *(float4*)&gws[i] = *(const float4*)&gw[i];
    __syncthreads();

    int warp = tid >> 5, lane = tid & 31;
    int n = blockIdx.x * 8 + warp;
    const float* xp = x + (size_t)n * H_DIM;

    float acc[E_NUM];
#pragma unroll
    for (int e = 0; e < E_NUM; e++) acc[e] = 0.f;
    for (int h = lane * 4; h < H_DIM; h += 128) {
        float4 xv = *(const float4*)&xp[h];
#pragma unroll
        for (int e = 0; e < E_NUM; e++) {
            float4 wv = *(const float4*)&gws[e * H_DIM + h];
            acc[e] += xv.x * wv.x + xv.y * wv.y + xv.z * wv.z + xv.w * wv.w;
        }
    }
#pragma unroll
    for (int e = 0; e < E_NUM; e++)
#pragma unroll
        for (int o = 16; o; o >>= 1) acc[e] += __shfl_xor_sync(~0u, acc[e], o);

    if (lane == 0) {
        float m = acc[0];
#pragma unroll
        for (int e = 1; e < E_NUM; e++) m = fmaxf(m, acc[e]);
        float p[E_NUM];
#pragma unroll
        for (int e = 0; e < E_NUM; e++) p[e] = expf(acc[e] - m);
        int i0 = 0; float b0 = p[0];
#pragma unroll
        for (int e = 1; e < E_NUM; e++) if (p[e] > b0) { b0 = p[e]; i0 = e; }
        int i1 = -1; float b1 = -1.f;
#pragma unroll
        for (int e = 0; e < E_NUM; e++)
            if (e != i0 && p[e] > b1) { b1 = p[e]; i1 = e; }
        float s2 = b0 + b1;
        g_top_i[2 * n] = i0; g_top_i[2 * n + 1] = i1;
        g_top_w[2 * n] = b0 / s2; g_top_w[2 * n + 1] = b1 / s2;
        atomicOr(&g_primary_mask, 1 << i0);
    }
}

// ---------------- kernel 2: reroute + merge + compaction ----------------
__global__ void route_kernel(const float* __restrict__ sim) {
    __shared__ int map_s[E_NUM];
    __shared__ int cnt_s[E_NUM];
    int tid = threadIdx.x;
    int mask = g_primary_mask;

    if (tid < E_NUM) {
        int mp;
        if ((mask >> tid) & 1) {
            mp = tid;
        } else {
            float best = -1e30f; int bj = -1;
            for (int j = 0; j < E_NUM; j++)
                if ((mask >> j) & 1) {
                    float v = sim[tid * E_NUM + j];
                    if (v > best) { best = v; bj = j; }
                }
            mp = (bj >= 0 && best >= THRESHOLD) ? bj : tid;
        }
        map_s[tid] = mp;
    }
    __syncthreads();

    for (int n = tid; n < N_TOK; n += 256) {
        int i0 = g_top_i[2 * n], i1 = g_top_i[2 * n + 1];
        float w0 = g_top_w[2 * n], w1 = g_top_w[2 * n + 1];
        int e0 = map_s[i0], e1 = map_s[i1];
        if (e0 == e1) { w0 += w1; e1 = -1; }
        g_tok_e[2 * n] = e0; g_tok_e[2 * n + 1] = e1;
        g_tok_w[2 * n] = w0; g_tok_w[2 * n + 1] = w1;
    }
    __syncthreads();

    int warp = tid >> 5, lane = tid & 31;
    int e = warp;
    int cnt = 0;
    for (int base = 0; base < N_TOK; base += 32) {
        int n = base + lane;
        int e0 = g_tok_e[2 * n], e1 = g_tok_e[2 * n + 1];
        bool f0 = (e0 == e), f1 = (e1 == e);
        bool f = f0 || f1;
        float w = f0 ? g_tok_w[2 * n] : g_tok_w[2 * n + 1];
        unsigned b = __ballot_sync(~0u, f);
        if (f) {
            int pos = cnt + __popc(b & ((1u << lane) - 1));
            g_list_tok[e][pos] = n;
            g_list_w[e][pos] = w;
        }
        cnt += __popc(b);
    }
    if (lane == 0) cnt_s[e] = cnt;
    __syncthreads();
    if (tid == 0) {
        int o = 0;
        for (int i = 0; i < E_NUM; i++) { g_off[i] = o; g_cnt[i] = cnt_s[i]; o += cnt_s[i]; }
    }
}

// ---------------- kernel 3: HMMA grouped GEMM gate_up + silu*u ----------
// grid (16 fblk, 16 mblk, 8 e), block 256 (8 warps)
// warps 0-3: gate (64 cols), warps 4-7: up (same 64 cols); silu fused via smem exchange
__global__ __launch_bounds__(256, 2)
void gemm_gu_mma(const float* __restrict__ x, const float* __restrict__ gup) {
    int e = blockIdx.z;
    int cnt = g_cnt[e];
    int mbase = blockIdx.y * 128;
    if (mbase >= cnt) return;
    int fb = blockIdx.x * 64;
    int off = g_off[e];

    extern __shared__ char smem[];
    __half* AH = (__half*)(smem + OFF_AH);
    __half* AL = (__half*)(smem + OFF_AL);
    __half* BH = (__half*)(smem + OFF_BH);
    __half* BL = (__half*)(smem + OFF_BL);
    uint32_t sb = smem_u32(smem);

    int tid = threadIdx.x, w = tid >> 5, lid = tid & 31;

    // global load mapping: 2 threads per row, 16 floats each
    int arow = tid >> 1, aseg = (tid & 1) * 16;
    int srow = mbase + arow; if (srow >= cnt) srow = cnt - 1;
    const float* aptr = x + (size_t)g_list_tok[e][srow] * H_DIM;
    int grow = (arow < 64) ? (fb + arow) : (F_DIM + fb + (arow - 64));
    const float* bptr = gup + ((size_t)e * 2 * F_DIM + grow) * H_DIM;

    // warp tiling: gate/up groups of 4 warps, each 2(M)x2(N32) grid
    int gw = w & 3;
    int wm = (gw & 1) * 64;
    int wn = (gw >> 1) * 32;
    int brow0 = ((w < 4) ? 0 : 64) + wn;

    int arow_l = (lid & 7) + ((lid & 8) ? 8 : 0);
    int acol_l = (lid & 16) ? 8 : 0;
    int brow_l = (lid & 7) + ((lid & 16) ? 8 : 0);
    int bcol_l = (lid & 8) ? 8 : 0;

    float c[4][4][4];
#pragma unroll
    for (int i = 0; i < 4; i++)
#pragma unroll
        for (int j = 0; j < 4; j++)
#pragma unroll
            for (int k = 0; k < 4; k++) c[i][j][k] = 0.f;

    for (int kc = 0; kc < 32; kc++) {
        int k0 = kc * 32;
        const float* ap = aptr + k0 + aseg;
        const float* bp = bptr + k0 + aseg;
        float4 a0 = *(const float4*)(ap + 0), a1 = *(const float4*)(ap + 4);
        float4 a2 = *(const float4*)(ap + 8), a3 = *(const float4*)(ap + 12);
        float4 b0 = *(const float4*)(bp + 0), b1 = *(const float4*)(bp + 4);
        float4 b2 = *(const float4*)(bp + 8), b3 = *(const float4*)(bp + 12);
        uint4 H0, L0, H1, L1;
        cvt8(a0, a1, H0, L0); cvt8(a2, a3, H1, L1);
        *(uint4*)&AH[arow * LDK + aseg] = H0;
        *(uint4*)&AH[arow * LDK + aseg + 8] = H1;
        *(uint4*)&AL[arow * LDK + aseg] = L0;
        *(uint4*)&AL[arow * LDK + aseg + 8] = L1;
        cvt8(b0, b1, H0, L0); cvt8(b2, b3, H1, L1);
        *(uint4*)&BH[arow * LDK + aseg] = H0;
        *(uint4*)&BH[arow * LDK + aseg + 8] = H1;
        *(uint4*)&BL[arow * LDK + aseg] = L0;
        *(uint4*)&BL[arow * LDK + aseg + 8] = L1;
        __syncthreads();

#pragma unroll
        for (int ks = 0; ks < 32; ks += 16) {
            uint32_t bh[8], bl[8];
            uint32_t ba = sb + OFF_BH + 2 * ((brow0 + brow_l) * LDK + ks + bcol_l);
            ldm4(bh, ba); ldm4(bh + 4, ba + 2 * 16 * LDK);
            ldm4(bl, ba + (OFF_BL - OFF_BH)); ldm4(bl + 4, ba + (OFF_BL - OFF_BH) + 2 * 16 * LDK);
#pragma unroll
            for (int mt = 0; mt < 4; mt++) {
                uint32_t aa = sb + OFF_AH + 2 * ((wm + mt * 16 + arow_l) * LDK + ks + acol_l);
                uint32_t ah[4], al[4];
                ldm4(ah, aa);
                mma16816(c[mt][0], ah, bh); mma16816(c[mt][1], ah, bh + 2);
                mma16816(c[mt][2], ah, bh + 4); mma16816(c[mt][3], ah, bh + 6);
                mma16816(c[mt][0], ah, bl); mma16816(c[mt][1], ah, bl + 2);
                mma16816(c[mt][2], ah, bl + 4); mma16816(c[mt][3], ah, bl + 6);
                ldm4(al, aa + (OFF_AL - OFF_AH));
                mma16816(c[mt][0], al, bh); mma16816(c[mt][1], al, bh + 2);
                mma16816(c[mt][2], al, bh + 4); mma16816(c[mt][3], al, bh + 6);
            }
        }
        __syncthreads();
    }

    // epilogue: up warps stash u into smem, gate warps read + silu*u -> g_mid
    float* su = (float*)smem;
    const int LDU = 66;
    if (w >= 4) {
#pragma unroll
        for (int mt = 0; mt < 4; mt++)
#pragma unroll
            for (int nt = 0; nt < 4; nt++) {
                int r0 = wm + mt * 16 + (lid >> 2);
                int cc = wn + nt * 8 + (lid & 3) * 2;
                *(float2*)&su[r0 * LDU + cc] = make_float2(c[mt][nt][0], c[mt][nt][1]);
                *(float2*)&su[(r0 + 8) * LDU + cc] = make_float2(c[mt][nt][2], c[mt][nt][3]);
            }
    }
    __syncthreads();
    if (w < 4) {
#pragma unroll
        for (int mt = 0; mt < 4; mt++)
#pragma unroll
            for (int nt = 0; nt < 4; nt++) {
                int r0 = wm + mt * 16 + (lid >> 2);
                int cc = wn + nt * 8 + (lid & 3) * 2;
#pragma unroll
                for (int half = 0; half < 2; half++) {
                    int r = r0 + half * 8;
                    int m = mbase + r;
                    if (m < cnt) {
                        float2 u = *(float2*)&su[r * LDU + cc];
                        float g0 = c[mt][nt][half * 2 + 0];
                        float g1 = c[mt][nt][half * 2 + 1];
                        float2 ov;
                        ov.x = (g0 / (1.f + expf(-g0))) * u.x;
                        ov.y = (g1 / (1.f + expf(-g1))) * u.y;
                        *(float2*)&g_mid[(size_t)(off + m) * F_DIM + fb + cc] = ov;
                    }
                }
            }
    }
}

// ---------------- kernel 4: HMMA grouped GEMM down + weighted scatter ----
// grid (8 hblk, 16 mblk, 8 e), block 256 (8 warps, 2x4 warp grid, 64x32 tiles)
__global__ __launch_bounds__(256, 2)
void gemm_down_mma(const float* __restrict__ dp, float* __restrict__ out) {
    int e = blockIdx.z;
    int cnt = g_cnt[e];
    int mbase = blockIdx.y * 128;
    if (mbase >= cnt) return;
    int hbase = blockIdx.x * 128;
    int off = g_off[e];

    extern __shared__ char smem[];
    __half* AH = (__half*)(smem + OFF_AH);
    __half* AL = (__half*)(smem + OFF_AL);
    __half* BH = (__half*)(smem + OFF_BH);
    __half* BL = (__half*)(smem + OFF_BL);
    uint32_t sb = smem_u32(smem);

    int tid = threadIdx.x, w = tid >> 5, lid = tid & 31;

    int arow = tid >> 1, aseg = (tid & 1) * 16;
    int srow = mbase + arow; if (srow >= cnt) srow = cnt - 1;
    const float* aptr = g_mid + (size_t)(off + srow) * F_DIM;
    const float* bptr = dp + ((size_t)e * H_DIM + hbase + arow) * F_DIM;

    int wm = (w & 1) * 64;
    int wn = (w >> 1) * 32;
    int brow0 = wn;

    int arow_l = (lid & 7) + ((lid & 8) ? 8 : 0);
    int acol_l = (lid & 16) ? 8 : 0;
    int brow_l = (lid & 7) + ((lid & 16) ? 8 : 0);
    int bcol_l = (lid & 8) ? 8 : 0;

    float c[4][4][4];
#pragma unroll
    for (int i = 0; i < 4; i++)
#pragma unroll
        for (int j = 0; j < 4; j++)
#pragma unroll
            for (int k = 0; k < 4; k++) c[i][j][k] = 0.f;

    for (int kc = 0; kc < 32; kc++) {
        int k0 = kc * 32;
        const float* ap = aptr + k0 + aseg;
        const float* bp = bptr + k0 + aseg;
        float4 a0 = *(const float4*)(ap + 0), a1 = *(const float4*)(ap + 4);
        float4 a2 = *(const float4*)(ap + 8), a3 = *(const float4*)(ap + 12);
        float4 b0 = *(const float4*)(bp + 0), b1 = *(const float4*)(bp + 4);
        float4 b2 = *(const float4*)(bp + 8), b3 = *(const float4*)(bp + 12);
        uint4 H0, L0, H1, L1;
        cvt8(a0, a1, H0, L0); cvt8(a2, a3, H1, L1);
        *(uint4*)&AH[arow * LDK + aseg] = H0;
        *(uint4*)&AH[arow * LDK + aseg + 8] = H1;
        *(uint4*)&AL[arow * LDK + aseg] = L0;
        *(uint4*)&AL[arow * LDK + aseg + 8] = L1;
        cvt8(b0, b1, H0, L0); cvt8(b2, b3, H1, L1);
        *(uint4*)&BH[arow * LDK + aseg] = H0;
        *(uint4*)&BH[arow * LDK + aseg + 8] = H1;
        *(uint4*)&BL[arow * LDK + aseg] = L0;
        *(uint4*)&BL[arow * LDK + aseg + 8] = L1;
        __syncthreads();

#pragma unroll
        for (int ks = 0; ks < 32; ks += 16) {
            uint32_t bh[8], bl[8];
            uint32_t ba = sb + OFF_BH + 2 * ((brow0 + brow_l) * LDK + ks + bcol_l);
            ldm4(bh, ba); ldm4(bh + 4, ba + 2 * 16 * LDK);
            ldm4(bl, ba + (OFF_BL - OFF_BH)); ldm4(bl + 4, ba + (OFF_BL - OFF_BH) + 2 * 16 * LDK);
#pragma unroll
            for (int mt = 0; mt < 4; mt++) {
                uint32_t aa = sb + OFF_AH + 2 * ((wm + mt * 16 + arow_l) * LDK + ks + acol_l);
                uint32_t ah[4], al[4];
                ldm4(ah, aa);
                mma16816(c[mt][0], ah, bh); mma16816(c[mt][1], ah, bh + 2);
                mma16816(c[mt][2], ah, bh + 4); mma16816(c[mt][3], ah, bh + 6);
                mma16816(c[mt][0], ah, bl); mma16816(c[mt][1], ah, bl + 2);
                mma16816(c[mt][2], ah, bl + 4); mma16816(c[mt][3], ah, bl + 6);
                ldm4(al, aa + (OFF_AL - OFF_AH));
                mma16816(c[mt][0], al, bh); mma16816(c[mt][1], al, bh + 2);
                mma16816(c[mt][2], al, bh + 4); mma16816(c[mt][3], al, bh + 6);
            }
        }
        __syncthreads();
    }

    // epilogue: weighted atomic scatter
#pragma unroll
    for (int mt = 0; mt < 4; mt++)
#pragma unroll
        for (int nt = 0; nt < 4; nt++) {
            int r0 = wm + mt * 16 + (lid >> 2);
            int cc = wn + nt * 8 + (lid & 3) * 2;
#pragma unroll
            for (int half = 0; half < 2; half++) {
                int m = mbase + r0 + half * 8;
                if (m < cnt) {
                    int tok = g_list_tok[e][m];
                    float wgt = g_list_w[e][m];
                    float* op = out + (size_t)tok * H_DIM + hbase + cc;
                    atomicAdd(op + 0, wgt * c[mt][nt][half * 2 + 0]);
                    atomicAdd(op + 1, wgt * c[mt][nt][half * 2 + 1]);
                }
            }
        }
}

// ---------------- launch ----------------
extern "C" void kernel_launch(void* const* d_in, const int* in_sizes, int n_in,
                              void* d_out, int out_size) {
    const float* x   = (const float*)d_in[0];
    const float* gw  = (const float*)d_in[1];
    const float* gup = (const float*)d_in[2];
    const float* dp  = (const float*)d_in[3];
    const float* sim = (const float*)d_in[4];
    float* out = (float*)d_out;

    zero_kernel<<<512, 256>>>(out);
    router_kernel<<<256, 256>>>(x, gw);
    route_kernel<<<1, 256>>>(sim);
    gemm_gu_mma<<<dim3(16, 16, 8), 256, SMEM_BYTES>>>(x, gup);
    gemm_down_mma<<<dim3(8, 16, 8), 256, SMEM_BYTES>>>(dp, out);
}

// round 9
// speedup vs baseline: 2.2867x; 1.4387x over previous
#include <cuda_runtime.h>
#include <cuda_fp16.h>
#include <math.h>
#include <stdint.h>

// Problem constants
#define N_TOK 2048
#define H_DIM 1024
#define E_NUM 8
#define F_DIM 1024
#define THRESHOLD 0.7f

// GEMM: CTA 128(M) x 256(N), K chunks of 32, 8 warps (warp tile 64x64), 3-stage cp.async
#define BUF_BYTES 61440      // AH 10240 + AL 10240 + BH 20480 + BL 20480
#define STAGES 3
#define SMEM_BYTES (BUF_BYTES * STAGES)

// ---------------- device globals (scratch; no allocation allowed) ----------
__device__ __half g_xh[2097152],  g_xl[2097152];     // x split
__device__ __half g_guph[16777216], g_gupl[16777216]; // gate_up split
__device__ __half g_dph[8388608],  g_dpl[8388608];   // down split
__device__ __half g_midh[4194304], g_midl[4194304];  // mid split (written by gu)
__device__ float  g_y[4194304];                      // per-slot down output
__device__ int    g_primary_mask;
__device__ int    g_top_i[N_TOK * 2];
__device__ float  g_top_w[N_TOK * 2];
__device__ int    g_tok_e[N_TOK * 2];
__device__ float  g_tok_w[N_TOK * 2];
__device__ int    g_list_tok[E_NUM][N_TOK];
__device__ float  g_list_w[E_NUM][N_TOK];
__device__ int    g_cnt[E_NUM], g_off[E_NUM];
__device__ int    g_nslot[N_TOK];
__device__ int    g_slot[N_TOK * 2];
__device__ float  g_wslot[N_TOK * 2];

// ---------------- helpers ----------------
__device__ __forceinline__ uint32_t smem_u32(const void* p) {
    uint32_t a;
    asm("{ .reg .u64 t; cvta.to.shared.u64 t, %1; cvt.u32.u64 %0, t; }" : "=r"(a) : "l"(p));
    return a;
}
__device__ __forceinline__ void ldm4(uint32_t* r, uint32_t addr) {
    asm volatile("ldmatrix.sync.aligned.m8n8.x4.shared.b16 {%0,%1,%2,%3}, [%4];"
                 : "=r"(r[0]), "=r"(r[1]), "=r"(r[2]), "=r"(r[3]) : "r"(addr));
}
__device__ __forceinline__ void mma16816(float* c, const uint32_t* a, const uint32_t* b) {
    asm volatile("mma.sync.aligned.m16n8k16.row.col.f32.f16.f16.f32 "
                 "{%0,%1,%2,%3}, {%4,%5,%6,%7}, {%8,%9}, {%0,%1,%2,%3};"
                 : "+f"(c[0]), "+f"(c[1]), "+f"(c[2]), "+f"(c[3])
                 : "r"(a[0]), "r"(a[1]), "r"(a[2]), "r"(a[3]), "r"(b[0]), "r"(b[1]));
}
__device__ __forceinline__ void cpasync16(uint32_t saddr, const void* g) {
    asm volatile("cp.async.cg.shared.global [%0], [%1], 16;" :: "r"(saddr), "l"(g) : "memory");
}
#define CP_COMMIT() asm volatile("cp.async.commit_group;" ::: "memory")
#define CP_WAIT2()  asm volatile("cp.async.wait_group 2;" ::: "memory")

__device__ __forceinline__ uint32_t pk(__half x, __half y) {
    __half2 t = __halves2half2(x, y);
    return *reinterpret_cast<uint32_t*>(&t);
}
// split 8 floats -> packed fp16 hi + fp16 lo residual
__device__ __forceinline__ void cvt8(float4 a, float4 b, uint4& H, uint4& L) {
    float f[8] = {a.x, a.y, a.z, a.w, b.x, b.y, b.z, b.w};
    __half h[8], l[8];
#pragma unroll
    for (int i = 0; i < 8; i++) {
        h[i] = __float2half_rn(f[i]);
        l[i] = __float2half_rn(f[i] - __half2float(h[i]));
    }
    H = make_uint4(pk(h[0], h[1]), pk(h[2], h[3]), pk(h[4], h[5]), pk(h[6], h[7]));
    L = make_uint4(pk(l[0], l[1]), pk(l[2], l[3]), pk(l[4], l[5]), pk(l[6], l[7]));
}

// ---------------- cvt kernels: fp32 -> half hi/lo ----------------
template<int S>
__global__ void cvt_kernel(const float4* __restrict__ src) {
    size_t i = (size_t)blockIdx.x * 256 + threadIdx.x;   // 8 floats per thread
    float4 a = src[2 * i], b = src[2 * i + 1];
    uint4 H, L;
    cvt8(a, b, H, L);
    uint4 *dh, *dl;
    if (S == 0)      { dh = (uint4*)g_xh;   dl = (uint4*)g_xl;   }
    else if (S == 1) { dh = (uint4*)g_guph; dl = (uint4*)g_gupl; }
    else             { dh = (uint4*)g_dph;  dl = (uint4*)g_dpl;  }
    dh[i] = H; dl[i] = L;
    if (S == 0 && blockIdx.x == 0 && threadIdx.x == 0) g_primary_mask = 0;
}

// ---------------- router ----------------
__global__ void router_kernel(const float* __restrict__ x,
                              const float* __restrict__ gw) {
    __shared__ __align__(16) float gws[E_NUM * H_DIM];
    int tid = threadIdx.x;
    for (int i = tid * 4; i < E_NUM * H_DIM; i += 1024)
        *(float4*)&gws[i] = *(const float4*)&gw[i];
    __syncthreads();

    int warp = tid >> 5, lane = tid & 31;
    int n = blockIdx.x * 8 + warp;
    const float* xp = x + (size_t)n * H_DIM;

    float acc[E_NUM];
#pragma unroll
    for (int e = 0; e < E_NUM; e++) acc[e] = 0.f;
    for (int h = lane * 4; h < H_DIM; h += 128) {
        float4 xv = *(const float4*)&xp[h];
#pragma unroll
        for (int e = 0; e < E_NUM; e++) {
            float4 wv = *(const float4*)&gws[e * H_DIM + h];
            acc[e] += xv.x * wv.x + xv.y * wv.y + xv.z * wv.z + xv.w * wv.w;
        }
    }
#pragma unroll
    for (int e = 0; e < E_NUM; e++)
#pragma unroll
        for (int o = 16; o; o >>= 1) acc[e] += __shfl_xor_sync(~0u, acc[e], o);

    if (lane == 0) {
        float m = acc[0];
#pragma unroll
        for (int e = 1; e < E_NUM; e++) m = fmaxf(m, acc[e]);
        float p[E_NUM];
#pragma unroll
        for (int e = 0; e < E_NUM; e++) p[e] = expf(acc[e] - m);
        int i0 = 0; float b0 = p[0];
#pragma unroll
        for (int e = 1; e < E_NUM; e++) if (p[e] > b0) { b0 = p[e]; i0 = e; }
        int i1 = -1; float b1 = -1.f;
#pragma unroll
        for (int e = 0; e < E_NUM; e++)
            if (e != i0 && p[e] > b1) { b1 = p[e]; i1 = e; }
        float s2 = b0 + b1;
        g_top_i[2 * n] = i0; g_top_i[2 * n + 1] = i1;
        g_top_w[2 * n] = b0 / s2; g_top_w[2 * n + 1] = b1 / s2;
        atomicOr(&g_primary_mask, 1 << i0);
    }
}

// ---------------- route: reroute + merge + compaction + slot map ---------
__global__ void route_kernel(const float* __restrict__ sim) {
    __shared__ int map_s[E_NUM];
    __shared__ int cnt_s[E_NUM];
    int tid = threadIdx.x;
    int mask = g_primary_mask;

    for (int n = tid; n < N_TOK; n += 256) g_nslot[n] = 0;

    if (tid < E_NUM) {
        int mp;
        if ((mask >> tid) & 1) {
            mp = tid;
        } else {
            float best = -1e30f; int bj = -1;
            for (int j = 0; j < E_NUM; j++)
                if ((mask >> j) & 1) {
                    float v = sim[tid * E_NUM + j];
                    if (v > best) { best = v; bj = j; }
                }
            mp = (bj >= 0 && best >= THRESHOLD) ? bj : tid;
        }
        map_s[tid] = mp;
    }
    __syncthreads();

    for (int n = tid; n < N_TOK; n += 256) {
        int i0 = g_top_i[2 * n], i1 = g_top_i[2 * n + 1];
        float w0 = g_top_w[2 * n], w1 = g_top_w[2 * n + 1];
        int e0 = map_s[i0], e1 = map_s[i1];
        if (e0 == e1) { w0 += w1; e1 = -1; }
        g_tok_e[2 * n] = e0; g_tok_e[2 * n + 1] = e1;
        g_tok_w[2 * n] = w0; g_tok_w[2 * n + 1] = w1;
    }
    __syncthreads();

    int warp = tid >> 5, lane = tid & 31;
    int e = warp;
    int cnt = 0;
    for (int base = 0; base < N_TOK; base += 32) {
        int n = base + lane;
        int e0 = g_tok_e[2 * n], e1 = g_tok_e[2 * n + 1];
        bool f0 = (e0 == e), f1 = (e1 == e);
        bool f = f0 || f1;
        float w = f0 ? g_tok_w[2 * n] : g_tok_w[2 * n + 1];
        unsigned b = __ballot_sync(~0u, f);
        if (f) {
            int pos = cnt + __popc(b & ((1u << lane) - 1));
            g_list_tok[e][pos] = n;
            g_list_w[e][pos] = w;
        }
        cnt += __popc(b);
    }
    if (lane == 0) cnt_s[e] = cnt;
    __syncthreads();
    if (tid == 0) {
        int o = 0;
        for (int i = 0; i < E_NUM; i++) { g_off[i] = o; g_cnt[i] = cnt_s[i]; o += cnt_s[i]; }
    }
    __syncthreads();
    // invert lists -> per-token slot map (order-independent: combine add commutes)
    for (int pos = lane; pos < cnt_s[e]; pos += 32) {
        int slot = g_off[e] + pos;
        int tok = g_list_tok[e][pos];
        int idx = atomicAdd(&g_nslot[tok], 1);
        g_slot[2 * tok + idx] = slot;
        g_wslot[2 * tok + idx] = g_list_w[e][pos];
    }
}

// ---------------- grouped GEMM (IS_GU: x@gup^T + silu*u -> mid; else mid@dp^T -> y)
// CTA 128M x 256N, 8 warps (2M x 4N of 64x64), K chunk 32, 3-stage cp.async
template<int IS_GU>
__global__ void __launch_bounds__(256, 1) gemm_mma() {
    int e = blockIdx.z;
    int cnt = g_cnt[e];
    int mbase = blockIdx.y * 128;
    if (mbase >= cnt) return;
    int nbx = blockIdx.x;
    int off = g_off[e];

    extern __shared__ char smem[];
    uint32_t sb = smem_u32(smem);
    int tid = threadIdx.x, w = tid >> 5, lid = tid & 31;

    // cp.async setup: per-thread 12 chunks of 16B per stage
    int rA0 = tid >> 2, seg = tid & 3;
    int sr0 = min(mbase + rA0, cnt - 1), sr1 = min(mbase + 64 + rA0, cnt - 1);
    const __half *Ah, *Al, *Bh, *Bl;
    uint32_t gA0, gA1;
    if (IS_GU) {
        gA0 = (uint32_t)g_list_tok[e][sr0] * 1024 + seg * 8;
        gA1 = (uint32_t)g_list_tok[e][sr1] * 1024 + seg * 8;
        Ah = g_xh; Al = g_xl; Bh = g_guph; Bl = g_gupl;
    } else {
        gA0 = (uint32_t)(off + sr0) * 1024 + seg * 8;
        gA1 = (uint32_t)(off + sr1) * 1024 + seg * 8;
        Ah = g_midh; Al = g_midl; Bh = g_dph; Bl = g_dpl;
    }
    uint32_t gB[4];
#pragma unroll
    for (int j = 0; j < 4; j++) {
        int rB = j * 64 + rA0;
        int grow;
        if (IS_GU) grow = (rB < 128) ? (nbx * 128 + rB) : (1024 + nbx * 128 + (rB - 128));
        else       grow = nbx * 256 + rB;
        gB[j] = (uint32_t)(e * (IS_GU ? 2048 : 1024) + grow) * 1024 + seg * 8;
    }
    uint32_t sA0 = rA0 * 80 + seg * 16;
    uint32_t sA1 = sA0 + 64 * 80;
    uint32_t sBb = 20480 + rA0 * 80 + seg * 16;

    auto issue = [&](int kc) {
        uint32_t bo = sb + (uint32_t)(kc % STAGES) * BUF_BYTES;
        uint32_t ko = (uint32_t)kc * 32;
        cpasync16(bo + sA0, Ah + gA0 + ko);
        cpasync16(bo + sA1, Ah + gA1 + ko);
        cpasync16(bo + 10240 + sA0, Al + gA0 + ko);
        cpasync16(bo + 10240 + sA1, Al + gA1 + ko);
#pragma unroll
        for (int j = 0; j < 4; j++) cpasync16(bo + sBb + j * 5120, Bh + gB[j] + ko);
#pragma unroll
        for (int j = 0; j < 4; j++) cpasync16(bo + 20480 + sBb + j * 5120, Bl + gB[j] + ko);
    };

    issue(0); CP_COMMIT();
    issue(1); CP_COMMIT();

    int wm = (w & 1) * 64, q = w >> 1;      // q: N quarter (0..3)
    int arow_l = lid & 15;
    int acol_l = (lid & 16) ? 8 : 0;
    int brow_l = (lid & 7) + ((lid & 16) ? 8 : 0);
    int bcol_l = (lid & 8) ? 8 : 0;

    float c[4][8][4];
#pragma unroll
    for (int i = 0; i < 4; i++)
#pragma unroll
        for (int j = 0; j < 8; j++)
#pragma unroll
            for (int k = 0; k < 4; k++) c[i][j][k] = 0.f;

    for (int kc = 0; kc < 32; kc++) {
        if (kc + 2 < 32) issue(kc + 2);
        CP_COMMIT();
        CP_WAIT2();
        __syncthreads();
        uint32_t bufb = sb + (uint32_t)(kc % STAGES) * BUF_BYTES;
#pragma unroll
        for (int ks = 0; ks < 32; ks += 16) {
            uint32_t bh[16], bl[16];
            uint32_t ba = bufb + 20480 + 2 * ((q * 64 + brow_l) * 40 + ks + bcol_l);
#pragma unroll
            for (int j = 0; j < 4; j++) {
                ldm4(bh + j * 4, ba + j * 16 * 80);
                ldm4(bl + j * 4, ba + 20480 + j * 16 * 80);
            }
#pragma unroll
            for (int mt = 0; mt < 4; mt++) {
                uint32_t aa = bufb + 2 * ((wm + mt * 16 + arow_l) * 40 + ks + acol_l);
                uint32_t ah[4], al[4];
                ldm4(ah, aa);
#pragma unroll
                for (int nn = 0; nn < 8; nn++) mma16816(c[mt][nn], ah, &bh[(nn >> 1) * 4 + (nn & 1) * 2]);
#pragma unroll
                for (int nn = 0; nn < 8; nn++) mma16816(c[mt][nn], ah, &bl[(nn >> 1) * 4 + (nn & 1) * 2]);
                ldm4(al, aa + 10240);
#pragma unroll
                for (int nn = 0; nn < 8; nn++) mma16816(c[mt][nn], al, &bh[(nn >> 1) * 4 + (nn & 1) * 2]);
            }
        }
        __syncthreads();
    }

    if (IS_GU) {
        // N cols 0..127 = gate (q 0,1), 128..255 = up (q 2,3); exchange u via smem
        float* su = (float*)smem;           // [128][132]
        const int LDU = 132;
        if (q >= 2) {
#pragma unroll
            for (int mt = 0; mt < 4; mt++)
#pragma unroll
                for (int nn = 0; nn < 8; nn++) {
                    int r = wm + mt * 16 + (lid >> 2);
                    int col = (q - 2) * 64 + nn * 8 + (lid & 3) * 2;
                    *(float2*)&su[r * LDU + col] = make_float2(c[mt][nn][0], c[mt][nn][1]);
                    *(float2*)&su[(r + 8) * LDU + col] = make_float2(c[mt][nn][2], c[mt][nn][3]);
                }
        }
        __syncthreads();
        if (q < 2) {
#pragma unroll
            for (int mt = 0; mt < 4; mt++)
#pragma unroll
                for (int nn = 0; nn < 8; nn++) {
                    int r0 = wm + mt * 16 + (lid >> 2);
                    int col = q * 64 + nn * 8 + (lid & 3) * 2;
#pragma unroll
                    for (int hf = 0; hf < 2; hf++) {
                        int r = r0 + hf * 8;
                        int m = mbase + r;
                        if (m < cnt) {
                            float2 u = *(float2*)&su[r * LDU + col];
                            float g0 = c[mt][nn][hf * 2 + 0];
                            float g1 = c[mt][nn][hf * 2 + 1];
                            float v0 = (g0 / (1.f + expf(-g0))) * u.x;
                            float v1 = (g1 / (1.f + expf(-g1))) * u.y;
                            size_t o = (size_t)(off + m) * F_DIM + nbx * 128 + col;
                            __half h0 = __float2half_rn(v0), h1 = __float2half_rn(v1);
                            *(__half2*)&g_midh[o] = __halves2half2(h0, h1);
                            *(__half2*)&g_midl[o] = __halves2half2(
                                __float2half_rn(v0 - __half2float(h0)),
                                __float2half_rn(v1 - __half2float(h1)));
                        }
                    }
                }
        }
    } else {
        // down: write per-slot result (no atomics; combine applies weights)
        int hb = nbx * 256;
#pragma unroll
        for (int mt = 0; mt < 4; mt++)
#pragma unroll
            for (int nn = 0; nn < 8; nn++) {
                int r0 = wm + mt * 16 + (lid >> 2);
                int col = q * 64 + nn * 8 + (lid & 3) * 2;
#pragma unroll
                for (int hf = 0; hf < 2; hf++) {
                    int m = mbase + r0 + hf * 8;
                    if (m < cnt) {
                        size_t o = (size_t)(off + m) * H_DIM + hb + col;
                        *(float2*)&g_y[o] = make_float2(c[mt][nn][hf * 2 + 0], c[mt][nn][hf * 2 + 1]);
                    }
                }
            }
    }
}

// ---------------- combine: out[tok] = sum_slots w * y[slot] ----------------
__global__ void combine_kernel(float* __restrict__ out) {
    int n = blockIdx.x;
    int h = threadIdx.x * 4;
    int ns = g_nslot[n];
    int s0 = g_slot[2 * n]; float w0 = g_wslot[2 * n];
    float4 y0 = *(const float4*)&g_y[(size_t)s0 * H_DIM + h];
    float4 r = make_float4(w0 * y0.x, w0 * y0.y, w0 * y0.z, w0 * y0.w);
    if (ns > 1) {
        int s1 = g_slot[2 * n + 1]; float w1 = g_wslot[2 * n + 1];
        float4 y1 = *(const float4*)&g_y[(size_t)s1 * H_DIM + h];
        r.x += w1 * y1.x; r.y += w1 * y1.y; r.z += w1 * y1.z; r.w += w1 * y1.w;
    }
    *(float4*)&out[(size_t)n * H_DIM + h] = r;
}

// ---------------- launch ----------------
extern "C" void kernel_launch(void* const* d_in, const int* in_sizes, int n_in,
                              void* d_out, int out_size) {
    const float* x   = (const float*)d_in[0];
    const float* gw  = (const float*)d_in[1];
    const float* gup = (const float*)d_in[2];
    const float* dp  = (const float*)d_in[3];
    const float* sim = (const float*)d_in[4];
    float* out = (float*)d_out;

    cudaFuncSetAttribute(gemm_mma<1>, cudaFuncAttributeMaxDynamicSharedMemorySize, SMEM_BYTES);
    cudaFuncSetAttribute(gemm_mma<0>, cudaFuncAttributeMaxDynamicSharedMemorySize, SMEM_BYTES);

    cvt_kernel<0><<<1024, 256>>>((const float4*)x);     // x:   2M floats
    cvt_kernel<1><<<8192, 256>>>((const float4*)gup);   // gup: 16.8M floats
    cvt_kernel<2><<<4096, 256>>>((const float4*)dp);    // dp:  8.4M floats
    router_kernel<<<256, 256>>>(x, gw);
    route_kernel<<<1, 256>>>(sim);
    gemm_mma<1><<<dim3(8, 16, 8), 256, SMEM_BYTES>>>();   // gate_up + silu*u
    gemm_mma<0><<<dim3(4, 16, 8), 256, SMEM_BYTES>>>();   // down -> y slots
    combine_kernel<<<N_TOK, 256>>>(out);
}

// round 10
// speedup vs baseline: 3.0483x; 1.3331x over previous
#include <cuda_runtime.h>
#include <cuda_fp16.h>
#include <math.h>
#include <stdint.h>

// Problem constants
#define N_TOK 2048
#define H_DIM 1024
#define E_NUM 8
#define F_DIM 1024
#define THRESHOLD 0.7f

// GEMM: CTA 128(M) x 256(N), K chunks of 32, 8 warps (warp tile 64x64), 4-stage cp.async
// Stage: AH 10240 + AL 10240 + BH 20480 (weights are fp16-hi only)
#define BUF_BYTES 40960
#define STAGES 4
#define SMEM_BYTES (BUF_BYTES * STAGES)   // 163840

// ---------------- device globals (scratch; no allocation allowed) ----------
__device__ __half g_xh[2097152],  g_xl[2097152];      // x split (activations: hi+lo)
__device__ __half g_guph[16777216];                   // gate_up hi only
__device__ __half g_dph[8388608];                     // down hi only
__device__ __half g_midh[4194304], g_midl[4194304];   // mid split (activation of down)
__device__ float  g_y[4194304];                       // per-slot down output
__device__ int    g_primary_mask;
__device__ int    g_top_i[N_TOK * 2];
__device__ float  g_top_w[N_TOK * 2];
__device__ int    g_tok_e[N_TOK * 2];
__device__ float  g_tok_w[N_TOK * 2];
__device__ int    g_list_tok[E_NUM][N_TOK];
__device__ float  g_list_w[E_NUM][N_TOK];
__device__ int    g_cnt[E_NUM], g_off[E_NUM];
__device__ int    g_nslot[N_TOK];
__device__ int    g_slot[N_TOK * 2];
__device__ float  g_wslot[N_TOK * 2];

// ---------------- helpers ----------------
__device__ __forceinline__ uint32_t smem_u32(const void* p) {
    uint32_t a;
    asm("{ .reg .u64 t; cvta.to.shared.u64 t, %1; cvt.u32.u64 %0, t; }" : "=r"(a) : "l"(p));
    return a;
}
__device__ __forceinline__ void ldm4(uint32_t* r, uint32_t addr) {
    asm volatile("ldmatrix.sync.aligned.m8n8.x4.shared.b16 {%0,%1,%2,%3}, [%4];"
                 : "=r"(r[0]), "=r"(r[1]), "=r"(r[2]), "=r"(r[3]) : "r"(addr));
}
__device__ __forceinline__ void mma16816(float* c, const uint32_t* a, const uint32_t* b) {
    asm volatile("mma.sync.aligned.m16n8k16.row.col.f32.f16.f16.f32 "
                 "{%0,%1,%2,%3}, {%4,%5,%6,%7}, {%8,%9}, {%0,%1,%2,%3};"
                 : "+f"(c[0]), "+f"(c[1]), "+f"(c[2]), "+f"(c[3])
                 : "r"(a[0]), "r"(a[1]), "r"(a[2]), "r"(a[3]), "r"(b[0]), "r"(b[1]));
}
__device__ __forceinline__ void cpasync16(uint32_t saddr, const void* g) {
    asm volatile("cp.async.cg.shared.global [%0], [%1], 16;" :: "r"(saddr), "l"(g) : "memory");
}
#define CP_COMMIT() asm volatile("cp.async.commit_group;" ::: "memory")
#define CP_WAIT3()  asm volatile("cp.async.wait_group 3;" ::: "memory")

__device__ __forceinline__ uint32_t pk(__half x, __half y) {
    __half2 t = __halves2half2(x, y);
    return *reinterpret_cast<uint32_t*>(&t);
}
// split 8 floats -> packed fp16 hi + fp16 lo residual
__device__ __forceinline__ void cvt8(float4 a, float4 b, uint4& H, uint4& L) {
    float f[8] = {a.x, a.y, a.z, a.w, b.x, b.y, b.z, b.w};
    __half h[8], l[8];
#pragma unroll
    for (int i = 0; i < 8; i++) {
        h[i] = __float2half_rn(f[i]);
        l[i] = __float2half_rn(f[i] - __half2float(h[i]));
    }
    H = make_uint4(pk(h[0], h[1]), pk(h[2], h[3]), pk(h[4], h[5]), pk(h[6], h[7]));
    L = make_uint4(pk(l[0], l[1]), pk(l[2], l[3]), pk(l[4], l[5]), pk(l[6], l[7]));
}
// hi-only variant for weights
__device__ __forceinline__ uint4 cvt8h(float4 a, float4 b) {
    float f[8] = {a.x, a.y, a.z, a.w, b.x, b.y, b.z, b.w};
    __half h[8];
#pragma unroll
    for (int i = 0; i < 8; i++) h[i] = __float2half_rn(f[i]);
    return make_uint4(pk(h[0], h[1]), pk(h[2], h[3]), pk(h[4], h[5]), pk(h[6], h[7]));
}

// ---------------- cvt kernels: fp32 -> half ----------------
// S=0: x -> hi+lo ; S=1: gup -> hi ; S=2: dp -> hi
template<int S>
__global__ void cvt_kernel(const float4* __restrict__ src) {
    size_t i = (size_t)blockIdx.x * 256 + threadIdx.x;   // 8 floats per thread
    float4 a = src[2 * i], b = src[2 * i + 1];
    if (S == 0) {
        uint4 H, L;
        cvt8(a, b, H, L);
        ((uint4*)g_xh)[i] = H;
        ((uint4*)g_xl)[i] = L;
        if (blockIdx.x == 0 && threadIdx.x == 0) g_primary_mask = 0;
    } else {
        uint4 H = cvt8h(a, b);
        if (S == 1) ((uint4*)g_guph)[i] = H;
        else        ((uint4*)g_dph)[i] = H;
    }
}

// ---------------- router ----------------
__global__ void router_kernel(const float* __restrict__ x,
                              const float* __restrict__ gw) {
    __shared__ __align__(16) float gws[E_NUM * H_DIM];
    int tid = threadIdx.x;
    for (int i = tid * 4; i < E_NUM * H_DIM; i += 1024)
        *(float4*)&gws[i] = *(const float4*)&gw[i];
    __syncthreads();

    int warp = tid >> 5, lane = tid & 31;
    int n = blockIdx.x * 8 + warp;
    const float* xp = x + (size_t)n * H_DIM;

    float acc[E_NUM];
#pragma unroll
    for (int e = 0; e < E_NUM; e++) acc[e] = 0.f;
    for (int h = lane * 4; h < H_DIM; h += 128) {
        float4 xv = *(const float4*)&xp[h];
#pragma unroll
        for (int e = 0; e < E_NUM; e++) {
            float4 wv = *(const float4*)&gws[e * H_DIM + h];
            acc[e] += xv.x * wv.x + xv.y * wv.y + xv.z * wv.z + xv.w * wv.w;
        }
    }
#pragma unroll
    for (int e = 0; e < E_NUM; e++)
#pragma unroll
        for (int o = 16; o; o >>= 1) acc[e] += __shfl_xor_sync(~0u, acc[e], o);

    if (lane == 0) {
        float m = acc[0];
#pragma unroll
        for (int e = 1; e < E_NUM; e++) m = fmaxf(m, acc[e]);
        float p[E_NUM];
#pragma unroll
        for (int e = 0; e < E_NUM; e++) p[e] = expf(acc[e] - m);
        int i0 = 0; float b0 = p[0];
#pragma unroll
        for (int e = 1; e < E_NUM; e++) if (p[e] > b0) { b0 = p[e]; i0 = e; }
        int i1 = -1; float b1 = -1.f;
#pragma unroll
        for (int e = 0; e < E_NUM; e++)
            if (e != i0 && p[e] > b1) { b1 = p[e]; i1 = e; }
        float s2 = b0 + b1;
        g_top_i[2 * n] = i0; g_top_i[2 * n + 1] = i1;
        g_top_w[2 * n] = b0 / s2; g_top_w[2 * n + 1] = b1 / s2;
        atomicOr(&g_primary_mask, 1 << i0);
    }
}

// ---------------- route: reroute + merge + compaction + slot map ---------
__global__ void route_kernel(const float* __restrict__ sim) {
    __shared__ int map_s[E_NUM];
    __shared__ int cnt_s[E_NUM];
    int tid = threadIdx.x;
    int mask = g_primary_mask;

    for (int n = tid; n < N_TOK; n += 256) g_nslot[n] = 0;

    if (tid < E_NUM) {
        int mp;
        if ((mask >> tid) & 1) {
            mp = tid;
        } else {
            float best = -1e30f; int bj = -1;
            for (int j = 0; j < E_NUM; j++)
                if ((mask >> j) & 1) {
                    float v = sim[tid * E_NUM + j];
                    if (v > best) { best = v; bj = j; }
                }
            mp = (bj >= 0 && best >= THRESHOLD) ? bj : tid;
        }
        map_s[tid] = mp;
    }
    __syncthreads();

    for (int n = tid; n < N_TOK; n += 256) {
        int i0 = g_top_i[2 * n], i1 = g_top_i[2 * n + 1];
        float w0 = g_top_w[2 * n], w1 = g_top_w[2 * n + 1];
        int e0 = map_s[i0], e1 = map_s[i1];
        if (e0 == e1) { w0 += w1; e1 = -1; }
        g_tok_e[2 * n] = e0; g_tok_e[2 * n + 1] = e1;
        g_tok_w[2 * n] = w0; g_tok_w[2 * n + 1] = w1;
    }
    __syncthreads();

    int warp = tid >> 5, lane = tid & 31;
    int e = warp;
    int cnt = 0;
    for (int base = 0; base < N_TOK; base += 32) {
        int n = base + lane;
        int e0 = g_tok_e[2 * n], e1 = g_tok_e[2 * n + 1];
        bool f0 = (e0 == e), f1 = (e1 == e);
        bool f = f0 || f1;
        float w = f0 ? g_tok_w[2 * n] : g_tok_w[2 * n + 1];
        unsigned b = __ballot_sync(~0u, f);
        if (f) {
            int pos = cnt + __popc(b & ((1u << lane) - 1));
            g_list_tok[e][pos] = n;
            g_list_w[e][pos] = w;
        }
        cnt += __popc(b);
    }
    if (lane == 0) cnt_s[e] = cnt;
    __syncthreads();
    if (tid == 0) {
        int o = 0;
        for (int i = 0; i < E_NUM; i++) { g_off[i] = o; g_cnt[i] = cnt_s[i]; o += cnt_s[i]; }
    }
    __syncthreads();
    // invert lists -> per-token slot map (order-independent: combine add commutes)
    for (int pos = lane; pos < cnt_s[e]; pos += 32) {
        int slot = g_off[e] + pos;
        int tok = g_list_tok[e][pos];
        int idx = atomicAdd(&g_nslot[tok], 1);
        g_slot[2 * tok + idx] = slot;
        g_wslot[2 * tok + idx] = g_list_w[e][pos];
    }
}

// ---------------- grouped GEMM (IS_GU: x@gup^T + silu*u -> mid; else mid@dp^T -> y)
// CTA 128M x 256N, 8 warps (2M x 4N of 64x64), K chunk 32, 4-stage cp.async
// 2-pass split: (a_hi + a_lo) x b_hi
template<int IS_GU>
__global__ void __launch_bounds__(256, 1) gemm_mma() {
    int e = blockIdx.z;
    int cnt = g_cnt[e];
    int mbase = blockIdx.y * 128;
    if (mbase >= cnt) return;
    int nbx = blockIdx.x;
    int off = g_off[e];

    extern __shared__ char smem[];
    uint32_t sb = smem_u32(smem);
    int tid = threadIdx.x, w = tid >> 5, lid = tid & 31;

    // cp.async setup: per-thread 8 chunks of 16B per stage
    int rA0 = tid >> 2, seg = tid & 3;
    int sr0 = min(mbase + rA0, cnt - 1), sr1 = min(mbase + 64 + rA0, cnt - 1);
    const __half *Ah, *Al, *Bh;
    uint32_t gA0, gA1;
    if (IS_GU) {
        gA0 = (uint32_t)g_list_tok[e][sr0] * 1024 + seg * 8;
        gA1 = (uint32_t)g_list_tok[e][sr1] * 1024 + seg * 8;
        Ah = g_xh; Al = g_xl; Bh = g_guph;
    } else {
        gA0 = (uint32_t)(off + sr0) * 1024 + seg * 8;
        gA1 = (uint32_t)(off + sr1) * 1024 + seg * 8;
        Ah = g_midh; Al = g_midl; Bh = g_dph;
    }
    uint32_t gB[4];
#pragma unroll
    for (int j = 0; j < 4; j++) {
        int rB = j * 64 + rA0;
        int grow;
        if (IS_GU) grow = (rB < 128) ? (nbx * 128 + rB) : (1024 + nbx * 128 + (rB - 128));
        else       grow = nbx * 256 + rB;
        gB[j] = (uint32_t)(e * (IS_GU ? 2048 : 1024) + grow) * 1024 + seg * 8;
    }
    uint32_t sA0 = rA0 * 80 + seg * 16;
    uint32_t sA1 = sA0 + 64 * 80;
    uint32_t sBb = 20480 + rA0 * 80 + seg * 16;

    auto issue = [&](int kc) {
        uint32_t bo = sb + (uint32_t)(kc & 3) * BUF_BYTES;
        uint32_t ko = (uint32_t)kc * 32;
        cpasync16(bo + sA0, Ah + gA0 + ko);
        cpasync16(bo + sA1, Ah + gA1 + ko);
        cpasync16(bo + 10240 + sA0, Al + gA0 + ko);
        cpasync16(bo + 10240 + sA1, Al + gA1 + ko);
#pragma unroll
        for (int j = 0; j < 4; j++) cpasync16(bo + sBb + j * 5120, Bh + gB[j] + ko);
    };

    issue(0); CP_COMMIT();
    issue(1); CP_COMMIT();
    issue(2); CP_COMMIT();

    int wm = (w & 1) * 64, q = w >> 1;      // q: N quarter (0..3)
    int arow_l = lid & 15;
    int acol_l = (lid & 16) ? 8 : 0;
    int brow_l = (lid & 7) + ((lid & 16) ? 8 : 0);
    int bcol_l = (lid & 8) ? 8 : 0;

    float c[4][8][4];
#pragma unroll
    for (int i = 0; i < 4; i++)
#pragma unroll
        for (int j = 0; j < 8; j++)
#pragma unroll
            for (int k = 0; k < 4; k++) c[i][j][k] = 0.f;

    for (int kc = 0; kc < 32; kc++) {
        if (kc + 3 < 32) issue(kc + 3);
        CP_COMMIT();
        CP_WAIT3();
        __syncthreads();
        uint32_t bufb = sb + (uint32_t)(kc & 3) * BUF_BYTES;
#pragma unroll
        for (int ks = 0; ks < 32; ks += 16) {
            uint32_t bh[16];
            uint32_t ba = bufb + 20480 + 2 * ((q * 64 + brow_l) * 40 + ks + bcol_l);
#pragma unroll
            for (int j = 0; j < 4; j++) ldm4(bh + j * 4, ba + j * 16 * 80);
#pragma unroll
            for (int mt = 0; mt < 4; mt++) {
                uint32_t aa = bufb + 2 * ((wm + mt * 16 + arow_l) * 40 + ks + acol_l);
                uint32_t ah[4], al[4];
                ldm4(ah, aa);
#pragma unroll
                for (int nn = 0; nn < 8; nn++) mma16816(c[mt][nn], ah, &bh[(nn >> 1) * 4 + (nn & 1) * 2]);
                ldm4(al, aa + 10240);
#pragma unroll
                for (int nn = 0; nn < 8; nn++) mma16816(c[mt][nn], al, &bh[(nn >> 1) * 4 + (nn & 1) * 2]);
            }
        }
        __syncthreads();
    }

    if (IS_GU) {
        // N cols 0..127 = gate (q 0,1), 128..255 = up (q 2,3); exchange u via smem
        float* su = (float*)smem;           // [128][132]
        const int LDU = 132;
        if (q >= 2) {
#pragma unroll
            for (int mt = 0; mt < 4; mt++)
#pragma unroll
                for (int nn = 0; nn < 8; nn++) {
                    int r = wm + mt * 16 + (lid >> 2);
                    int col = (q - 2) * 64 + nn * 8 + (lid & 3) * 2;
                    *(float2*)&su[r * LDU + col] = make_float2(c[mt][nn][0], c[mt][nn][1]);
                    *(float2*)&su[(r + 8) * LDU + col] = make_float2(c[mt][nn][2], c[mt][nn][3]);
                }
        }
        __syncthreads();
        if (q < 2) {
#pragma unroll
            for (int mt = 0; mt < 4; mt++)
#pragma unroll
                for (int nn = 0; nn < 8; nn++) {
                    int r0 = wm + mt * 16 + (lid >> 2);
                    int col = q * 64 + nn * 8 + (lid & 3) * 2;
#pragma unroll
                    for (int hf = 0; hf < 2; hf++) {
                        int r = r0 + hf * 8;
                        int m = mbase + r;
                        if (m < cnt) {
                            float2 u = *(float2*)&su[r * LDU + col];
                            float g0 = c[mt][nn][hf * 2 + 0];
                            float g1 = c[mt][nn][hf * 2 + 1];
                            float v0 = (g0 / (1.f + expf(-g0))) * u.x;
                            float v1 = (g1 / (1.f + expf(-g1))) * u.y;
                            size_t o = (size_t)(off + m) * F_DIM + nbx * 128 + col;
                            __half h0 = __float2half_rn(v0), h1 = __float2half_rn(v1);
                            *(__half2*)&g_midh[o] = __halves2half2(h0, h1);
                            *(__half2*)&g_midl[o] = __halves2half2(
                                __float2half_rn(v0 - __half2float(h0)),
                                __float2half_rn(v1 - __half2float(h1)));
                        }
                    }
                }
        }
    } else {
        // down: write per-slot result (no atomics; combine applies weights)
        int hb = nbx * 256;
#pragma unroll
        for (int mt = 0; mt < 4; mt++)
#pragma unroll
            for (int nn = 0; nn < 8; nn++) {
                int r0 = wm + mt * 16 + (lid >> 2);
                int col = q * 64 + nn * 8 + (lid & 3) * 2;
#pragma unroll
                for (int hf = 0; hf < 2; hf++) {
                    int m = mbase + r0 + hf * 8;
                    if (m < cnt) {
                        size_t o = (size_t)(off + m) * H_DIM + hb + col;
                        *(float2*)&g_y[o] = make_float2(c[mt][nn][hf * 2 + 0], c[mt][nn][hf * 2 + 1]);
                    }
                }
            }
    }
}

// ---------------- combine: out[tok] = sum_slots w * y[slot] ----------------
__global__ void combine_kernel(float* __restrict__ out) {
    int n = blockIdx.x;
    int h = threadIdx.x * 4;
    int ns = g_nslot[n];
    int s0 = g_slot[2 * n]; float w0 = g_wslot[2 * n];
    float4 y0 = *(const float4*)&g_y[(size_t)s0 * H_DIM + h];
    float4 r = make_float4(w0 * y0.x, w0 * y0.y, w0 * y0.z, w0 * y0.w);
    if (ns > 1) {
        int s1 = g_slot[2 * n + 1]; float w1 = g_wslot[2 * n + 1];
        float4 y1 = *(const float4*)&g_y[(size_t)s1 * H_DIM + h];
        r.x += w1 * y1.x; r.y += w1 * y1.y; r.z += w1 * y1.z; r.w += w1 * y1.w;
    }
    *(float4*)&out[(size_t)n * H_DIM + h] = r;
}

// ---------------- launch ----------------
extern "C" void kernel_launch(void* const* d_in, const int* in_sizes, int n_in,
                              void* d_out, int out_size) {
    const float* x   = (const float*)d_in[0];
    const float* gw  = (const float*)d_in[1];
    const float* gup = (const float*)d_in[2];
    const float* dp  = (const float*)d_in[3];
    const float* sim = (const float*)d_in[4];
    float* out = (float*)d_out;

    cudaFuncSetAttribute(gemm_mma<1>, cudaFuncAttributeMaxDynamicSharedMemorySize, SMEM_BYTES);
    cudaFuncSetAttribute(gemm_mma<0>, cudaFuncAttributeMaxDynamicSharedMemorySize, SMEM_BYTES);

    cvt_kernel<0><<<1024, 256>>>((const float4*)x);     // x:   2M floats -> hi+lo
    cvt_kernel<1><<<8192, 256>>>((const float4*)gup);   // gup: 16.8M floats -> hi
    cvt_kernel<2><<<4096, 256>>>((const float4*)dp);    // dp:  8.4M floats -> hi
    router_kernel<<<256, 256>>>(x, gw);
    route_kernel<<<1, 256>>>(sim);
    gemm_mma<1><<<dim3(8, 16, 8), 256, SMEM_BYTES>>>();   // gate_up + silu*u
    gemm_mma<0><<<dim3(4, 16, 8), 256, SMEM_BYTES>>>();   // down -> y slots
    combine_kernel<<<N_TOK, 256>>>(out);
}

// round 12
// speedup vs baseline: 4.0199x; 1.3187x over previous
#include <cuda_runtime.h>
#include <cuda_fp16.h>
#include <math.h>
#include <stdint.h>

// Problem constants
#define N_TOK 2048
#define H_DIM 1024
#define E_NUM 8
#define F_DIM 1024
#define THRESHOLD 0.7f

// GEMM: CTA 128(M) x 256(N), K chunks of 32, 8 warps (warp tile 64x64), 4-stage cp.async
// Stage: AH 10240 + BH 20480 (pure fp16, single pass)
#define BUF_BYTES 30720
#define STAGES 4
#define SMEM_BYTES (BUF_BYTES * STAGES)   // 122880

// ---------------- device globals (scratch; no allocation allowed) ----------
__device__ __half g_xh[2097152];                      // x fp16
__device__ __half g_guph[16777216];                   // gate_up fp16
__device__ __half g_dph[8388608];                     // down fp16
__device__ __half g_midh[4194304];                    // mid fp16 (written by gu)
__device__ float  g_y[4194304];                       // per-slot down output
__device__ int    g_primary_mask;
__device__ int    g_top_i[N_TOK * 2];
__device__ float  g_top_w[N_TOK * 2];
__device__ int    g_tok_e[N_TOK * 2];
__device__ float  g_tok_w[N_TOK * 2];
__device__ int    g_list_tok[E_NUM][N_TOK];
__device__ float  g_list_w[E_NUM][N_TOK];
__device__ int    g_cnt[E_NUM], g_off[E_NUM];
__device__ int    g_nslot[N_TOK];
__device__ int    g_slot[N_TOK * 2];
__device__ float  g_wslot[N_TOK * 2];

// ---------------- helpers ----------------
__device__ __forceinline__ uint32_t smem_u32(const void* p) {
    uint32_t a;
    asm("{ .reg .u64 t; cvta.to.shared.u64 t, %1; cvt.u32.u64 %0, t; }" : "=r"(a) : "l"(p));
    return a;
}
__device__ __forceinline__ void ldm4(uint32_t* r, uint32_t addr) {
    asm volatile("ldmatrix.sync.aligned.m8n8.x4.shared.b16 {%0,%1,%2,%3}, [%4];"
                 : "=r"(r[0]), "=r"(r[1]), "=r"(r[2]), "=r"(r[3]) : "r"(addr));
}
__device__ __forceinline__ void mma16816(float* c, const uint32_t* a, const uint32_t* b) {
    asm volatile("mma.sync.aligned.m16n8k16.row.col.f32.f16.f16.f32 "
                 "{%0,%1,%2,%3}, {%4,%5,%6,%7}, {%8,%9}, {%0,%1,%2,%3};"
                 : "+f"(c[0]), "+f"(c[1]), "+f"(c[2]), "+f"(c[3])
                 : "r"(a[0]), "r"(a[1]), "r"(a[2]), "r"(a[3]), "r"(b[0]), "r"(b[1]));
}
__device__ __forceinline__ void cpasync16(uint32_t saddr, const void* g) {
    asm volatile("cp.async.cg.shared.global [%0], [%1], 16;" :: "r"(saddr), "l"(g) : "memory");
}
#define CP_COMMIT() asm volatile("cp.async.commit_group;" ::: "memory")
#define CP_WAIT3()  asm volatile("cp.async.wait_group 3;" ::: "memory")

__device__ __forceinline__ uint32_t pk(__half x, __half y) {
    __half2 t = __halves2half2(x, y);
    return *reinterpret_cast<uint32_t*>(&t);
}
// 8 floats -> packed fp16 (rn)
__device__ __forceinline__ uint4 cvt8h(float4 a, float4 b) {
    float f[8] = {a.x, a.y, a.z, a.w, b.x, b.y, b.z, b.w};
    __half h[8];
#pragma unroll
    for (int i = 0; i < 8; i++) h[i] = __float2half_rn(f[i]);
    return make_uint4(pk(h[0], h[1]), pk(h[2], h[3]), pk(h[4], h[5]), pk(h[6], h[7]));
}

// ---------------- cvt kernels: fp32 -> fp16 ----------------
// S=0: x ; S=1: gup ; S=2: dp
template<int S>
__global__ void cvt_kernel(const float4* __restrict__ src) {
    size_t i = (size_t)blockIdx.x * 256 + threadIdx.x;   // 8 floats per thread
    float4 a = src[2 * i], b = src[2 * i + 1];
    uint4 H = cvt8h(a, b);
    if (S == 0) {
        ((uint4*)g_xh)[i] = H;
        if (blockIdx.x == 0 && threadIdx.x == 0) g_primary_mask = 0;
    } else if (S == 1) {
        ((uint4*)g_guph)[i] = H;
    } else {
        ((uint4*)g_dph)[i] = H;
    }
}

// ---------------- router ----------------
__global__ void router_kernel(const float* __restrict__ x,
                              const float* __restrict__ gw) {
    __shared__ __align__(16) float gws[E_NUM * H_DIM];
    int tid = threadIdx.x;
    for (int i = tid * 4; i < E_NUM * H_DIM; i += 1024)
        *(float4*)&gws[i] = *(const float4*)&gw[i];
    __syncthreads();

    int warp = tid >> 5, lane = tid & 31;
    int n = blockIdx.x * 8 + warp;
    const float* xp = x + (size_t)n * H_DIM;

    float acc[E_NUM];
#pragma unroll
    for (int e = 0; e < E_NUM; e++) acc[e] = 0.f;
    for (int h = lane * 4; h < H_DIM; h += 128) {
        float4 xv = *(const float4*)&xp[h];
#pragma unroll
        for (int e = 0; e < E_NUM; e++) {
            float4 wv = *(const float4*)&gws[e * H_DIM + h];
            acc[e] += xv.x * wv.x + xv.y * wv.y + xv.z * wv.z + xv.w * wv.w;
        }
    }
#pragma unroll
    for (int e = 0; e < E_NUM; e++)
#pragma unroll
        for (int o = 16; o; o >>= 1) acc[e] += __shfl_xor_sync(~0u, acc[e], o);

    if (lane == 0) {
        float m = acc[0];
#pragma unroll
        for (int e = 1; e < E_NUM; e++) m = fmaxf(m, acc[e]);
        float p[E_NUM];
#pragma unroll
        for (int e = 0; e < E_NUM; e++) p[e] = expf(acc[e] - m);
        int i0 = 0; float b0 = p[0];
#pragma unroll
        for (int e = 1; e < E_NUM; e++) if (p[e] > b0) { b0 = p[e]; i0 = e; }
        int i1 = -1; float b1 = -1.f;
#pragma unroll
        for (int e = 0; e < E_NUM; e++)
            if (e != i0 && p[e] > b1) { b1 = p[e]; i1 = e; }
        float s2 = b0 + b1;
        g_top_i[2 * n] = i0; g_top_i[2 * n + 1] = i1;
        g_top_w[2 * n] = b0 / s2; g_top_w[2 * n + 1] = b1 / s2;
        atomicOr(&g_primary_mask, 1 << i0);
    }
}

// ---------------- route: reroute + merge + compaction + slot map ---------
__global__ void route_kernel(const float* __restrict__ sim) {
    __shared__ int map_s[E_NUM];
    __shared__ int cnt_s[E_NUM];
    int tid = threadIdx.x;
    int mask = g_primary_mask;

    for (int n = tid; n < N_TOK; n += 256) g_nslot[n] = 0;

    if (tid < E_NUM) {
        int mp;
        if ((mask >> tid) & 1) {
            mp = tid;
        } else {
            float best = -1e30f; int bj = -1;
            for (int j = 0; j < E_NUM; j++)
                if ((mask >> j) & 1) {
                    float v = sim[tid * E_NUM + j];
                    if (v > best) { best = v; bj = j; }
                }
            mp = (bj >= 0 && best >= THRESHOLD) ? bj : tid;
        }
        map_s[tid] = mp;
    }
    __syncthreads();

    for (int n = tid; n < N_TOK; n += 256) {
        int i0 = g_top_i[2 * n], i1 = g_top_i[2 * n + 1];
        float w0 = g_top_w[2 * n], w1 = g_top_w[2 * n + 1];
        int e0 = map_s[i0], e1 = map_s[i1];
        if (e0 == e1) { w0 += w1; e1 = -1; }
        g_tok_e[2 * n] = e0; g_tok_e[2 * n + 1] = e1;
        g_tok_w[2 * n] = w0; g_tok_w[2 * n + 1] = w1;
    }
    __syncthreads();

    int warp = tid >> 5, lane = tid & 31;
    int e = warp;
    int cnt = 0;
    for (int base = 0; base < N_TOK; base += 32) {
        int n = base + lane;
        int e0 = g_tok_e[2 * n], e1 = g_tok_e[2 * n + 1];
        bool f0 = (e0 == e), f1 = (e1 == e);
        bool f = f0 || f1;
        float w = f0 ? g_tok_w[2 * n] : g_tok_w[2 * n + 1];
        unsigned b = __ballot_sync(~0u, f);
        if (f) {
            int pos = cnt + __popc(b & ((1u << lane) - 1));
            g_list_tok[e][pos] = n;
            g_list_w[e][pos] = w;
        }
        cnt += __popc(b);
    }
    if (lane == 0) cnt_s[e] = cnt;
    __syncthreads();
    if (tid == 0) {
        int o = 0;
        for (int i = 0; i < E_NUM; i++) { g_off[i] = o; g_cnt[i] = cnt_s[i]; o += cnt_s[i]; }
    }
    __syncthreads();
    // invert lists -> per-token slot map (order-independent: combine add commutes)
    for (int pos = lane; pos < cnt_s[e]; pos += 32) {
        int slot = g_off[e] + pos;
        int tok = g_list_tok[e][pos];
        int idx = atomicAdd(&g_nslot[tok], 1);
        g_slot[2 * tok + idx] = slot;
        g_wslot[2 * tok + idx] = g_list_w[e][pos];
    }
}

// ---------------- grouped GEMM (IS_GU: x@gup^T + silu*u -> mid; else mid@dp^T -> y)
// CTA 128M x 256N, 8 warps (2M x 4N of 64x64), K chunk 32, 4-stage cp.async, pure fp16
template<int IS_GU>
__global__ void __launch_bounds__(256, 1) gemm_mma() {
    int e = blockIdx.z;
    int cnt = g_cnt[e];
    int mbase = blockIdx.y * 128;
    if (mbase >= cnt) return;
    int nbx = blockIdx.x;
    int off = g_off[e];

    extern __shared__ char smem[];
    uint32_t sb = smem_u32(smem);
    int tid = threadIdx.x, w = tid >> 5, lid = tid & 31;

    // cp.async setup: per-thread 6 chunks of 16B per stage
    int rA0 = tid >> 2, seg = tid & 3;
    int sr0 = min(mbase + rA0, cnt - 1), sr1 = min(mbase + 64 + rA0, cnt - 1);
    const __half *Ah, *Bh;
    uint32_t gA0, gA1;
    if (IS_GU) {
        gA0 = (uint32_t)g_list_tok[e][sr0] * 1024 + seg * 8;
        gA1 = (uint32_t)g_list_tok[e][sr1] * 1024 + seg * 8;
        Ah = g_xh; Bh = g_guph;
    } else {
        gA0 = (uint32_t)(off + sr0) * 1024 + seg * 8;
        gA1 = (uint32_t)(off + sr1) * 1024 + seg * 8;
        Ah = g_midh; Bh = g_dph;
    }
    uint32_t gB[4];
#pragma unroll
    for (int j = 0; j < 4; j++) {
        int rB = j * 64 + rA0;
        int grow;
        if (IS_GU) grow = (rB < 128) ? (nbx * 128 + rB) : (1024 + nbx * 128 + (rB - 128));
        else       grow = nbx * 256 + rB;
        gB[j] = (uint32_t)(e * (IS_GU ? 2048 : 1024) + grow) * 1024 + seg * 8;
    }
    uint32_t sA0 = rA0 * 80 + seg * 16;
    uint32_t sA1 = sA0 + 64 * 80;
    uint32_t sBb = 10240 + rA0 * 80 + seg * 16;

    auto issue = [&](int kc) {
        uint32_t bo = sb + (uint32_t)(kc & 3) * BUF_BYTES;
        uint32_t ko = (uint32_t)kc * 32;
        cpasync16(bo + sA0, Ah + gA0 + ko);
        cpasync16(bo + sA1, Ah + gA1 + ko);
#pragma unroll
        for (int j = 0; j < 4; j++) cpasync16(bo + sBb + j * 5120, Bh + gB[j] + ko);
    };

    issue(0); CP_COMMIT();
    issue(1); CP_COMMIT();
    issue(2); CP_COMMIT();

    int wm = (w & 1) * 64, q = w >> 1;      // q: N quarter (0..3)
    int arow_l = lid & 15;
    int acol_l = (lid & 16) ? 8 : 0;
    int brow_l = (lid & 7) + ((lid & 16) ? 8 : 0);
    int bcol_l = (lid & 8) ? 8 : 0;

    float c[4][8][4];
#pragma unroll
    for (int i = 0; i < 4; i++)
#pragma unroll
        for (int j = 0; j < 8; j++)
#pragma unroll
            for (int k = 0; k < 4; k++) c[i][j][k] = 0.f;

    for (int kc = 0; kc < 32; kc++) {
        if (kc + 3 < 32) issue(kc + 3);
        CP_COMMIT();
        CP_WAIT3();
        __syncthreads();
        uint32_t bufb = sb + (uint32_t)(kc & 3) * BUF_BYTES;
#pragma unroll
        for (int ks = 0; ks < 32; ks += 16) {
            uint32_t bh[16];
            uint32_t ba = bufb + 10240 + 2 * ((q * 64 + brow_l) * 40 + ks + bcol_l);
#pragma unroll
            for (int j = 0; j < 4; j++) ldm4(bh + j * 4, ba + j * 16 * 80);
#pragma unroll
            for (int mt = 0; mt < 4; mt++) {
                uint32_t aa = bufb + 2 * ((wm + mt * 16 + arow_l) * 40 + ks + acol_l);
                uint32_t ah[4];
                ldm4(ah, aa);
#pragma unroll
                for (int nn = 0; nn < 8; nn++) mma16816(c[mt][nn], ah, &bh[(nn >> 1) * 4 + (nn & 1) * 2]);
            }
        }
        __syncthreads();
    }

    if (IS_GU) {
        // N cols 0..127 = gate (q 0,1), 128..255 = up (q 2,3); exchange u via smem
        float* su = (float*)smem;           // [128][132]
        const int LDU = 132;
        if (q >= 2) {
#pragma unroll
            for (int mt = 0; mt < 4; mt++)
#pragma unroll
                for (int nn = 0; nn < 8; nn++) {
                    int r = wm + mt * 16 + (lid >> 2);
                    int col = (q - 2) * 64 + nn * 8 + (lid & 3) * 2;
                    *(float2*)&su[r * LDU + col] = make_float2(c[mt][nn][0], c[mt][nn][1]);
                    *(float2*)&su[(r + 8) * LDU + col] = make_float2(c[mt][nn][2], c[mt][nn][3]);
                }
        }
        __syncthreads();
        if (q < 2) {
#pragma unroll
            for (int mt = 0; mt < 4; mt++)
#pragma unroll
                for (int nn = 0; nn < 8; nn++) {
                    int r0 = wm + mt * 16 + (lid >> 2);
                    int col = q * 64 + nn * 8 + (lid & 3) * 2;
#pragma unroll
                    for (int hf = 0; hf < 2; hf++) {
                        int r = r0 + hf * 8;
                        int m = mbase + r;
                        if (m < cnt) {
                            float2 u = *(float2*)&su[r * LDU + col];
                            float g0 = c[mt][nn][hf * 2 + 0];
                            float g1 = c[mt][nn][hf * 2 + 1];
                            float v0 = (g0 / (1.f + expf(-g0))) * u.x;
                            float v1 = (g1 / (1.f + expf(-g1))) * u.y;
                            size_t o = (size_t)(off + m) * F_DIM + nbx * 128 + col;
                            *(__half2*)&g_midh[o] = __halves2half2(
                                __float2half_rn(v0), __float2half_rn(v1));
                        }
                    }
                }
        }
    } else {
        // down: write per-slot result (no atomics; combine applies weights)
        int hb = nbx * 256;
#pragma unroll
        for (int mt = 0; mt < 4; mt++)
#pragma unroll
            for (int nn = 0; nn < 8; nn++) {
                int r0 = wm + mt * 16 + (lid >> 2);
                int col = q * 64 + nn * 8 + (lid & 3) * 2;
#pragma unroll
                for (int hf = 0; hf < 2; hf++) {
                    int m = mbase + r0 + hf * 8;
                    if (m < cnt) {
                        size_t o = (size_t)(off + m) * H_DIM + hb + col;
                        *(float2*)&g_y[o] = make_float2(c[mt][nn][hf * 2 + 0], c[mt][nn][hf * 2 + 1]);
                    }
                }
            }
    }
}

// ---------------- combine: out[tok] = sum_slots w * y[slot] ----------------
__global__ void combine_kernel(float* __restrict__ out) {
    int n = blockIdx.x;
    int h = threadIdx.x * 4;
    int ns = g_nslot[n];
    int s0 = g_slot[2 * n]; float w0 = g_wslot[2 * n];
    float4 y0 = *(const float4*)&g_y[(size_t)s0 * H_DIM + h];
    float4 r = make_float4(w0 * y0.x, w0 * y0.y, w0 * y0.z, w0 * y0.w);
    if (ns > 1) {
        int s1 = g_slot[2 * n + 1]; float w1 = g_wslot[2 * n + 1];
        float4 y1 = *(const float4*)&g_y[(size_t)s1 * H_DIM + h];
        r.x += w1 * y1.x; r.y += w1 * y1.y; r.z += w1 * y1.z; r.w += w1 * y1.w;
    }
    *(float4*)&out[(size_t)n * H_DIM + h] = r;
}

// ---------------- launch ----------------
extern "C" void kernel_launch(void* const* d_in, const int* in_sizes, int n_in,
                              void* d_out, int out_size) {
    const float* x   = (const float*)d_in[0];
    const float* gw  = (const float*)d_in[1];
    const float* gup = (const float*)d_in[2];
    const float* dp  = (const float*)d_in[3];
    const float* sim = (const float*)d_in[4];
    float* out = (float*)d_out;

    cudaFuncSetAttribute(gemm_mma<1>, cudaFuncAttributeMaxDynamicSharedMemorySize, SMEM_BYTES);
    cudaFuncSetAttribute(gemm_mma<0>, cudaFuncAttributeMaxDynamicSharedMemorySize, SMEM_BYTES);

    cvt_kernel<0><<<1024, 256>>>((const float4*)x);     // x:   2M floats -> fp16
    cvt_kernel<1><<<8192, 256>>>((const float4*)gup);   // gup: 16.8M floats -> fp16
    cvt_kernel<2><<<4096, 256>>>((const float4*)dp);    // dp:  8.4M floats -> fp16
    router_kernel<<<256, 256>>>(x, gw);
    route_kernel<<<1, 256>>>(sim);
    gemm_mma<1><<<dim3(8, 16, 8), 256, SMEM_BYTES>>>();   // gate_up + silu*u
    gemm_mma<0><<<dim3(4, 16, 8), 256, SMEM_BYTES>>>();   // down -> y slots
    combine_kernel<<<N_TOK, 256>>>(out);
}